// round 14
// baseline (speedup 1.0000x reference)
#include <cuda_runtime.h>
#include <math.h>
#include <stdint.h>

#define NG 512
#define IMG_H 256
#define IMG_W 256
#define TW 16
#define TH 8
#define NPIX 128          // pixels per tile
#define NTHR 256          // raster: 2 threads per pixel (2 composite segments)

#define FXC 256.0f
#define FYC 256.0f
#define LIMX (1.3f * 0.5f)
#define LIMY (1.3f * 0.5f)

// Depth-sorted per-gaussian data (stable (depth, id) order == ref argsort):
__device__ float4 sA[NG];      // px, py, ca, cb
__device__ float4 sB[NG];      // cc, op, cr, cg
__device__ float4 sC[NG];      // cb(blue), invdepth, depth, pad
__device__ float4 sCull[NG];   // px, py, r2, pad

// ---------------------------------------------------------------------------
// Preprocess + rank-sort fused: 16 blocks x 256 threads; 8 threads per
// gaussian. Each block smem-fills all 512 depths (2 loads/thread); each
// octet computes the heavy math redundantly (MUFU idle -> free), each octet
// thread ranks one 64-entry slice of the depth table, shfl-combines (3
// butterflies), and lane 0 scatters straight into the depth-sorted arrays.
// ---------------------------------------------------------------------------
__global__ void __launch_bounds__(256)
preprocess_kernel(const float* __restrict__ means3D,
                  const float* __restrict__ opac,
                  const float* __restrict__ colors,
                  const float* __restrict__ scales,
                  const float* __restrict__ rots,
                  const float* __restrict__ view,
                  const float* __restrict__ proj,
                  float* __restrict__ radii_out)
{
    __shared__ __align__(16) float sdep[NG];
    const int tid = threadIdx.x;
    const int j = blockIdx.x * 32 + (tid >> 3);   // gaussian id
    const int r = tid & 7;                        // octet sub-lane

    const float V00 = view[0], V01 = view[1], V02 = view[2],  V03 = view[3];
    const float V10 = view[4], V11 = view[5], V12 = view[6],  V13 = view[7];
    const float V20 = view[8], V21 = view[9], V22 = view[10], V23 = view[11];

    // All 512 depths, cooperatively (2 per thread)
    #pragma unroll
    for (int t = tid; t < NG; t += 256) {
        const float a0 = means3D[3 * t + 0];
        const float a1 = means3D[3 * t + 1];
        const float a2 = means3D[3 * t + 2];
        sdep[t] = V20 * a0 + V21 * a1 + V22 * a2 + V23;
    }
    __syncthreads();

    const float m0 = means3D[3 * j + 0];
    const float m1 = means3D[3 * j + 1];
    const float m2 = means3D[3 * j + 2];

    const float t0 = V00 * m0 + V01 * m1 + V02 * m2 + V03;
    const float t1 = V10 * m0 + V11 * m1 + V12 * m2 + V13;
    const float depth = sdep[j];

    const float c0 = proj[0]  * m0 + proj[1]  * m1 + proj[2]  * m2 + proj[3];
    const float c1 = proj[4]  * m0 + proj[5]  * m1 + proj[6]  * m2 + proj[7];
    const float c3 = proj[12] * m0 + proj[13] * m1 + proj[14] * m2 + proj[15];
    const float pw = __fdividef(1.0f, c3 + 1e-7f);
    const float px = ((c0 * pw + 1.0f) * (float)IMG_W - 1.0f) * 0.5f;
    const float py = ((c1 * pw + 1.0f) * (float)IMG_H - 1.0f) * 0.5f;

    const float4 q = reinterpret_cast<const float4*>(rots)[j];
    float qw = q.x, qx = q.y, qy = q.z, qz = q.w;
    const float qn = rsqrtf(qw * qw + qx * qx + qy * qy + qz * qz);
    qw *= qn; qx *= qn; qy *= qn; qz *= qn;
    const float R00 = 1.0f - 2.0f * (qy * qy + qz * qz);
    const float R01 = 2.0f * (qx * qy - qw * qz);
    const float R02 = 2.0f * (qx * qz + qw * qy);
    const float R10 = 2.0f * (qx * qy + qw * qz);
    const float R11 = 1.0f - 2.0f * (qx * qx + qz * qz);
    const float R12 = 2.0f * (qy * qz - qw * qx);
    const float R20 = 2.0f * (qx * qz - qw * qy);
    const float R21 = 2.0f * (qy * qz + qw * qx);
    const float R22 = 1.0f - 2.0f * (qx * qx + qy * qy);

    const float s0 = scales[3 * j + 0];
    const float s1 = scales[3 * j + 1];
    const float s2 = scales[3 * j + 2];

    const float M00 = R00 * s0, M01 = R01 * s1, M02 = R02 * s2;
    const float M10 = R10 * s0, M11 = R11 * s1, M12 = R12 * s2;
    const float M20 = R20 * s0, M21 = R21 * s1, M22 = R22 * s2;
    const float C00 = M00 * M00 + M01 * M01 + M02 * M02;
    const float C01 = M00 * M10 + M01 * M11 + M02 * M12;
    const float C02 = M00 * M20 + M01 * M21 + M02 * M22;
    const float C11 = M10 * M10 + M11 * M11 + M12 * M12;
    const float C12 = M10 * M20 + M11 * M21 + M12 * M22;
    const float C22 = M20 * M20 + M21 * M21 + M22 * M22;

    const float invz = __fdividef(1.0f, depth);
    const float ttx = fminf(fmaxf(t0 * invz, -LIMX), LIMX) * depth;
    const float tty = fminf(fmaxf(t1 * invz, -LIMY), LIMY) * depth;
    const float J00 = FXC * invz;
    const float J02 = -FXC * ttx * invz * invz;
    const float J11 = FYC * invz;
    const float J12 = -FYC * tty * invz * invz;

    const float T00 = J00 * V00 + J02 * V20;
    const float T01 = J00 * V01 + J02 * V21;
    const float T02 = J00 * V02 + J02 * V22;
    const float T10 = J11 * V10 + J12 * V20;
    const float T11 = J11 * V11 + J12 * V21;
    const float T12 = J11 * V12 + J12 * V22;

    const float u0 = C00 * T00 + C01 * T01 + C02 * T02;
    const float u1 = C01 * T00 + C11 * T01 + C12 * T02;
    const float u2 = C02 * T00 + C12 * T01 + C22 * T02;
    const float w0 = C00 * T10 + C01 * T11 + C02 * T12;
    const float w1 = C01 * T10 + C11 * T11 + C12 * T12;
    const float w2 = C02 * T10 + C12 * T11 + C22 * T12;
    const float a = T00 * u0 + T01 * u1 + T02 * u2 + 0.3f;
    const float b = T10 * u0 + T11 * u1 + T12 * u2;
    const float c = T10 * w0 + T11 * w1 + T12 * w2 + 0.3f;

    const float det = a * c - b * b;
    const float inv_det = __fdividef(1.0f, (det != 0.0f) ? det : 1.0f);
    const float ca =  c * inv_det;
    const float cb = -b * inv_det;
    const float cc =  a * inv_det;

    const float mid = 0.5f * (a + c);
    const float lam = mid + sqrtf(fmaxf(mid * mid - det, 0.1f));

    const bool valid = (depth > 0.2f) && (det > 0.0f);
    const float op = opac[j];

    // Exact cull radius^2: alpha < 1/255 guaranteed beyond it.
    float r2 = -1.0f;
    if (valid && op * 255.0f > 1.0f) {
        r2 = 2.0f * lam * __logf(255.0f * op) + 1e-2f;
        if (r2 < 0.0f) r2 = -1.0f;
    }

    // Partial stable rank by (depth, id): this thread covers a 64-entry
    // slice [r*64, (r+1)*64).
    int rank = 0;
    const float4* sd4 = reinterpret_cast<const float4*>(sdep);
    const int kbeg = r * (NG / 32);               // 64 entries = 16 vec4
    #pragma unroll 4
    for (int k = 0; k < NG / 32; ++k) {
        const float4 dj = sd4[kbeg + k];
        const int jj = 4 * (kbeg + k);
        rank += (dj.x < depth) || ((dj.x == depth) && (jj + 0 < j));
        rank += (dj.y < depth) || ((dj.y == depth) && (jj + 1 < j));
        rank += (dj.z < depth) || ((dj.z == depth) && (jj + 2 < j));
        rank += (dj.w < depth) || ((dj.w == depth) && (jj + 3 < j));
    }
    // Combine octet partials (butterfly within the 8-lane group).
    rank += __shfl_xor_sync(0xFFFFFFFFu, rank, 1);
    rank += __shfl_xor_sync(0xFFFFFFFFu, rank, 2);
    rank += __shfl_xor_sync(0xFFFFFFFFu, rank, 4);

    if (r == 0) {
        radii_out[j] = (float)((int)ceilf(3.0f * sqrtf(lam)));
        sA[rank] = make_float4(px, py, ca, cb);
        sB[rank] = make_float4(cc, op, colors[3 * j + 0], colors[3 * j + 1]);
        sC[rank] = make_float4(colors[3 * j + 2],
                               __fdividef(1.0f, fmaxf(depth, 1e-6f)),
                               depth, 0.0f);
        sCull[rank] = make_float4(px, py, r2, 0.0f);
    }
}

// ---------------------------------------------------------------------------
// Raster (R12 config — best measured): each block = one 16x8 tile, 256
// threads = 2 composite segments per pixel. Ballot-cull the depth-sorted
// gaussians (bitmask is in depth order), warp-shfl prefix, compact (already
// sorted), then each pixel's two threads composite half the survivor list
// each and combine: final = part0 + T0*part1, T = T0*T1.
// ---------------------------------------------------------------------------
__global__ void __launch_bounds__(NTHR)
raster_kernel(const float* __restrict__ bg,
              const float* __restrict__ mask,
              float* __restrict__ out)
{
    __shared__ float4 ssA[NG];
    __shared__ float4 ssB[NG];
    __shared__ float4 ssC[NG];
    __shared__ uint32_t bm[NG / 32];
    __shared__ int wpre[NG / 32 + 1];
    __shared__ float sT1[NPIX], sR1[NPIX], sG1[NPIX], sB1[NPIX], sD1[NPIX];

    const int tid  = threadIdx.x;
    const int warp = tid >> 5;          // 0..7
    const int lane = tid & 31;

    const float tx0 = (float)(blockIdx.x * TW);
    const float tx1 = tx0 + (float)(TW - 1);
    const float ty0 = (float)(blockIdx.y * TH);
    const float ty1 = ty0 + (float)(TH - 1);

    // Phase 1: cull in sorted order. j = k*256 + tid -> word index k*8 + warp.
    #pragma unroll
    for (int k = 0; k < NG / NTHR; ++k) {
        const int j = k * NTHR + tid;
        const float4 cg = sCull[j];
        const float cx = fminf(fmaxf(cg.x, tx0), tx1);
        const float cy = fminf(fmaxf(cg.y, ty0), ty1);
        const float ddx = cg.x - cx;
        const float ddy = cg.y - cy;
        const uint32_t bal = __ballot_sync(0xFFFFFFFFu,
                                           ddx * ddx + ddy * ddy <= cg.z);
        if (lane == 0) bm[k * 8 + warp] = bal;
    }
    __syncthreads();

    // Warp-parallel exclusive prefix over 16 word-popcounts (warp 0).
    if (warp == 0) {
        int v = (lane < NG / 32) ? (int)__popc(bm[lane]) : 0;
        #pragma unroll
        for (int off = 1; off < NG / 32; off <<= 1) {
            const int n = __shfl_up_sync(0xFFFFFFFFu, v, off);
            if (lane >= off) v += n;
        }
        if (lane < NG / 32) wpre[lane + 1] = v;
        if (lane == 0) wpre[0] = 0;
    }
    __syncthreads();

    // Phase 2: compaction — sorted bitmask => ss* is depth-sorted directly.
    #pragma unroll
    for (int k = 0; k < NG / NTHR; ++k) {
        const int j = k * NTHR + tid;
        const uint32_t w = bm[j >> 5];
        const uint32_t bit = 1u << (j & 31);
        if (w & bit) {
            const int pos = wpre[j >> 5] + __popc(w & (bit - 1u));
            ssA[pos] = sA[j];
            ssB[pos] = sB[j];
            ssC[pos] = sC[j];
        }
    }
    __syncthreads();
    const int cnt = wpre[NG / 32];

    // Phase 3: segmented front-to-back composite. 2 threads per pixel.
    const int ppix = tid & (NPIX - 1);         // 0..127 local pixel
    const int seg  = tid >> 7;                 // 0 or 1
    const int x = blockIdx.x * TW + (ppix & (TW - 1));
    const int y = blockIdx.y * TH + (ppix >> 4);
    const float fx = (float)x;
    const float fy = (float)y;

    const int half = (cnt + 1) >> 1;
    const int nbeg = seg ? half : 0;
    const int nend = seg ? cnt : half;

    float T = 1.0f, aR = 0.0f, aG = 0.0f, aB = 0.0f, aD = 0.0f;

    for (int n = nbeg; n < nend; ++n) {
        const float4 A = ssA[n];
        const float dx = fx - A.x;
        const float dy = fy - A.y;
        const float4 B = ssB[n];
        const float power = -0.5f * (A.z * dx * dx) - A.w * dx * dy
                            - 0.5f * (B.x * dy * dy);
        if (power > 0.0f) continue;
        const float alpha = fminf(0.99f, B.y * __expf(power));
        if (alpha < (1.0f / 255.0f)) continue;
        const float4 C = ssC[n];
        const float w = alpha * T;
        aR += w * B.z;
        aG += w * B.w;
        aB += w * C.x;
        aD += w * C.y;
        T *= (1.0f - alpha);
        if (T < 1e-7f) break;
    }

    if (seg == 1) {
        sT1[ppix] = T; sR1[ppix] = aR; sG1[ppix] = aG;
        sB1[ppix] = aB; sD1[ppix] = aD;
    }
    __syncthreads();

    if (seg == 0) {
        const float T1 = sT1[ppix];
        const float fR = aR + T * sR1[ppix];
        const float fG = aG + T * sG1[ppix];
        const float fB = aB + T * sB1[ppix];
        const float fD = aD + T * sD1[ppix];
        const float Tf = T * T1;

        const int pix = y * IMG_W + x;
        const float m = mask[pix];
        const int HW = IMG_H * IMG_W;
        out[0 * HW + pix] = (fR + Tf * bg[0]) * m;
        out[1 * HW + pix] = (fG + Tf * bg[1]) * m;
        out[2 * HW + pix] = (fB + Tf * bg[2]) * m;
        out[3 * HW + NG + pix] = fD * m;   // invd after color(3*HW) + radii(NG)
    }
}

// ---------------------------------------------------------------------------
extern "C" void kernel_launch(void* const* d_in, const int* in_sizes, int n_in,
                              void* d_out, int out_size)
{
    const float* means3D = (const float*)d_in[0];
    // d_in[1] = means2D (unused by reference math)
    const float* opac    = (const float*)d_in[2];
    const float* colors  = (const float*)d_in[3];
    const float* scales  = (const float*)d_in[4];
    const float* rots    = (const float*)d_in[5];
    const float* view    = (const float*)d_in[6];
    const float* proj    = (const float*)d_in[7];
    const float* bg      = (const float*)d_in[8];
    const float* mask    = (const float*)d_in[9];
    float* out = (float*)d_out;

    float* radii_out = out + 3 * IMG_H * IMG_W;

    preprocess_kernel<<<16, 256>>>(means3D, opac, colors, scales, rots,
                                   view, proj, radii_out);

    dim3 blk(NTHR);
    dim3 grd(IMG_W / TW, IMG_H / TH);
    raster_kernel<<<grd, blk>>>(bg, mask, out);
}

// round 16
// speedup vs baseline: 1.0026x; 1.0026x over previous
#include <cuda_runtime.h>
#include <math.h>
#include <stdint.h>

#define NG 512
#define IMG_H 256
#define IMG_W 256
#define TW 16
#define TH 8
#define NPIX 128          // pixels per tile
#define NTHR 256          // 2 threads per pixel (2 composite segments)

#define FXC 256.0f
#define FYC 256.0f
#define LIMX (1.3f * 0.5f)
#define LIMY (1.3f * 0.5f)

// Depth-sorted per-gaussian data (stable (depth, id) order == ref argsort):
__device__ float4 sA[NG];      // px, py, ca, cb
__device__ float4 sB[NG];      // cc, op, cr, cg
__device__ float4 sC[NG];      // cb(blue), invdepth, depth, pad
__device__ float4 sCull[NG];   // px, py, r2, pad
// Monotonic arrival counter for the software grid barrier. Never reset:
// each launch consumes one 512-ticket epoch (ticket/512), so graph replays
// are self-synchronizing without cross-replay hazards.
__device__ unsigned int g_done = 0u;

// ---------------------------------------------------------------------------
// Single fused kernel, 512 blocks (= 512 gaussians = 512 tiles), 256 thr.
// Phase A (preprocess): block b computes gaussian b. 256 threads fill the
//   512-entry depth table (2 loads each); warp 0 does the heavy projection /
//   covariance math (lanes redundant), each lane ranks a 16-entry slice of
//   the depth table, a 5-step butterfly yields the exact stable (depth, id)
//   rank, and lane 0 scatters into the depth-sorted global arrays + radii.
// Barrier: threadfence + atomicAdd ticket; thread 0 spins (nanosleep) until
//   the epoch's 512 arrivals complete. All 512 CTAs are co-resident
//   (7 CTAs/SM smem capacity x 148 SMs = 1036 slots >= 512), so the spin
//   cannot deadlock — including under graph replay (monotonic epochs).
// Phase B (raster): proven R12 path — ballot-cull the depth-sorted
//   gaussians (bitmask in depth order), warp-shfl prefix, compact (already
//   sorted), 2-segment front-to-back composite per pixel.
// ---------------------------------------------------------------------------
__global__ void __launch_bounds__(NTHR)
fused_kernel(const float* __restrict__ means3D,
             const float* __restrict__ opac,
             const float* __restrict__ colors,
             const float* __restrict__ scales,
             const float* __restrict__ rots,
             const float* __restrict__ view,
             const float* __restrict__ proj,
             const float* __restrict__ bg,
             const float* __restrict__ mask,
             float* __restrict__ out)
{
    __shared__ __align__(16) float sdep[NG];
    __shared__ float4 ssA[NG];
    __shared__ float4 ssB[NG];
    __shared__ float4 ssC[NG];
    __shared__ uint32_t bm[NG / 32];
    __shared__ int wpre[NG / 32 + 1];
    __shared__ float sT1[NPIX], sR1[NPIX], sG1[NPIX], sB1[NPIX], sD1[NPIX];

    const int tid  = threadIdx.x;
    const int warp = tid >> 5;
    const int lane = tid & 31;
    const int bid  = blockIdx.y * gridDim.x + blockIdx.x;   // == gaussian id

    const float V00 = view[0], V01 = view[1], V02 = view[2],  V03 = view[3];
    const float V10 = view[4], V11 = view[5], V12 = view[6],  V13 = view[7];
    const float V20 = view[8], V21 = view[9], V22 = view[10], V23 = view[11];

    // ---- Phase A: depth table (2 loads/thread) ----
    #pragma unroll
    for (int t = tid; t < NG; t += NTHR) {
        const float a0 = means3D[3 * t + 0];
        const float a1 = means3D[3 * t + 1];
        const float a2 = means3D[3 * t + 2];
        sdep[t] = V20 * a0 + V21 * a1 + V22 * a2 + V23;
    }
    __syncthreads();

    // Warp 0: full preprocess of gaussian `bid` (lanes redundant), ranked
    // 16 entries per lane.
    if (warp == 0) {
        const int j = bid;
        const float m0 = means3D[3 * j + 0];
        const float m1 = means3D[3 * j + 1];
        const float m2 = means3D[3 * j + 2];

        const float t0 = V00 * m0 + V01 * m1 + V02 * m2 + V03;
        const float t1 = V10 * m0 + V11 * m1 + V12 * m2 + V13;
        const float depth = sdep[j];

        const float c0 = proj[0]  * m0 + proj[1]  * m1 + proj[2]  * m2 + proj[3];
        const float c1 = proj[4]  * m0 + proj[5]  * m1 + proj[6]  * m2 + proj[7];
        const float c3 = proj[12] * m0 + proj[13] * m1 + proj[14] * m2 + proj[15];
        const float pw = __fdividef(1.0f, c3 + 1e-7f);
        const float px = ((c0 * pw + 1.0f) * (float)IMG_W - 1.0f) * 0.5f;
        const float py = ((c1 * pw + 1.0f) * (float)IMG_H - 1.0f) * 0.5f;

        const float4 q = reinterpret_cast<const float4*>(rots)[j];
        float qw = q.x, qx = q.y, qy = q.z, qz = q.w;
        const float qn = rsqrtf(qw * qw + qx * qx + qy * qy + qz * qz);
        qw *= qn; qx *= qn; qy *= qn; qz *= qn;
        const float R00 = 1.0f - 2.0f * (qy * qy + qz * qz);
        const float R01 = 2.0f * (qx * qy - qw * qz);
        const float R02 = 2.0f * (qx * qz + qw * qy);
        const float R10 = 2.0f * (qx * qy + qw * qz);
        const float R11 = 1.0f - 2.0f * (qx * qx + qz * qz);
        const float R12 = 2.0f * (qy * qz - qw * qx);
        const float R20 = 2.0f * (qx * qz - qw * qy);
        const float R21 = 2.0f * (qy * qz + qw * qx);
        const float R22 = 1.0f - 2.0f * (qx * qx + qy * qy);

        const float s0 = scales[3 * j + 0];
        const float s1 = scales[3 * j + 1];
        const float s2 = scales[3 * j + 2];

        const float M00 = R00 * s0, M01 = R01 * s1, M02 = R02 * s2;
        const float M10 = R10 * s0, M11 = R11 * s1, M12 = R12 * s2;
        const float M20 = R20 * s0, M21 = R21 * s1, M22 = R22 * s2;
        const float C00 = M00 * M00 + M01 * M01 + M02 * M02;
        const float C01 = M00 * M10 + M01 * M11 + M02 * M12;
        const float C02 = M00 * M20 + M01 * M21 + M02 * M22;
        const float C11 = M10 * M10 + M11 * M11 + M12 * M12;
        const float C12 = M10 * M20 + M11 * M21 + M12 * M22;
        const float C22 = M20 * M20 + M21 * M21 + M22 * M22;

        const float invz = __fdividef(1.0f, depth);
        const float ttx = fminf(fmaxf(t0 * invz, -LIMX), LIMX) * depth;
        const float tty = fminf(fmaxf(t1 * invz, -LIMY), LIMY) * depth;
        const float J00 = FXC * invz;
        const float J02 = -FXC * ttx * invz * invz;
        const float J11 = FYC * invz;
        const float J12 = -FYC * tty * invz * invz;

        const float T00 = J00 * V00 + J02 * V20;
        const float T01 = J00 * V01 + J02 * V21;
        const float T02 = J00 * V02 + J02 * V22;
        const float T10 = J11 * V10 + J12 * V20;
        const float T11 = J11 * V11 + J12 * V21;
        const float T12 = J11 * V12 + J12 * V22;

        const float u0 = C00 * T00 + C01 * T01 + C02 * T02;
        const float u1 = C01 * T00 + C11 * T01 + C12 * T02;
        const float u2 = C02 * T00 + C12 * T01 + C22 * T02;
        const float w0 = C00 * T10 + C01 * T11 + C02 * T12;
        const float w1 = C01 * T10 + C11 * T11 + C12 * T12;
        const float w2 = C02 * T10 + C12 * T11 + C22 * T12;
        const float a = T00 * u0 + T01 * u1 + T02 * u2 + 0.3f;
        const float b = T10 * u0 + T11 * u1 + T12 * u2;
        const float c = T10 * w0 + T11 * w1 + T12 * w2 + 0.3f;

        const float det = a * c - b * b;
        const float inv_det = __fdividef(1.0f, (det != 0.0f) ? det : 1.0f);
        const float ca =  c * inv_det;
        const float cb = -b * inv_det;
        const float cc =  a * inv_det;

        const float mid = 0.5f * (a + c);
        const float lam = mid + sqrtf(fmaxf(mid * mid - det, 0.1f));

        const bool valid = (depth > 0.2f) && (det > 0.0f);
        const float op = opac[j];

        float r2 = -1.0f;
        if (valid && op * 255.0f > 1.0f) {
            r2 = 2.0f * lam * __logf(255.0f * op) + 1e-2f;
            if (r2 < 0.0f) r2 = -1.0f;
        }

        // Stable rank by (depth, id): lane covers 16 entries.
        int rank = 0;
        const float4* sd4 = reinterpret_cast<const float4*>(sdep);
        #pragma unroll
        for (int k = 0; k < 4; ++k) {
            const float4 dj = sd4[lane * 4 + k];
            const int jj = 4 * (lane * 4 + k);
            rank += (dj.x < depth) || ((dj.x == depth) && (jj + 0 < j));
            rank += (dj.y < depth) || ((dj.y == depth) && (jj + 1 < j));
            rank += (dj.z < depth) || ((dj.z == depth) && (jj + 2 < j));
            rank += (dj.w < depth) || ((dj.w == depth) && (jj + 3 < j));
        }
        #pragma unroll
        for (int off = 1; off < 32; off <<= 1)
            rank += __shfl_xor_sync(0xFFFFFFFFu, rank, off);

        if (lane == 0) {
            out[3 * IMG_H * IMG_W + j] = (float)((int)ceilf(3.0f * sqrtf(lam)));
            sA[rank] = make_float4(px, py, ca, cb);
            sB[rank] = make_float4(cc, op, colors[3 * j + 0], colors[3 * j + 1]);
            sC[rank] = make_float4(colors[3 * j + 2],
                                   __fdividef(1.0f, fmaxf(depth, 1e-6f)),
                                   depth, 0.0f);
            sCull[rank] = make_float4(px, py, r2, 0.0f);
        }
    }

    // ---- Software grid barrier (all 512 CTAs are co-resident) ----
    if (tid == 0) {
        __threadfence();                              // publish sA..sCull
        const unsigned int ticket = atomicAdd(&g_done, 1u);
        const unsigned int target = ticket - (ticket % (unsigned)NG)
                                    + (unsigned)NG;   // end of this epoch
        volatile unsigned int* p = &g_done;
        while (*p < target) __nanosleep(64);
    }
    __syncthreads();
    __threadfence();                                  // acquire

    const float tx0 = (float)(blockIdx.x * TW);
    const float tx1 = tx0 + (float)(TW - 1);
    const float ty0 = (float)(blockIdx.y * TH);
    const float ty1 = ty0 + (float)(TH - 1);

    // ---- Phase B1: cull in sorted order. j = k*256 + tid -> word k*8+warp.
    #pragma unroll
    for (int k = 0; k < NG / NTHR; ++k) {
        const int j = k * NTHR + tid;
        const float4 cg = sCull[j];
        const float cx = fminf(fmaxf(cg.x, tx0), tx1);
        const float cy = fminf(fmaxf(cg.y, ty0), ty1);
        const float ddx = cg.x - cx;
        const float ddy = cg.y - cy;
        const uint32_t bal = __ballot_sync(0xFFFFFFFFu,
                                           ddx * ddx + ddy * ddy <= cg.z);
        if (lane == 0) bm[k * 8 + warp] = bal;
    }
    __syncthreads();

    // Warp-parallel exclusive prefix over 16 word-popcounts (warp 0).
    if (warp == 0) {
        int v = (lane < NG / 32) ? (int)__popc(bm[lane]) : 0;
        #pragma unroll
        for (int off = 1; off < NG / 32; off <<= 1) {
            const int n = __shfl_up_sync(0xFFFFFFFFu, v, off);
            if (lane >= off) v += n;
        }
        if (lane < NG / 32) wpre[lane + 1] = v;
        if (lane == 0) wpre[0] = 0;
    }
    __syncthreads();

    // ---- Phase B2: compaction — ss* is depth-sorted directly.
    #pragma unroll
    for (int k = 0; k < NG / NTHR; ++k) {
        const int j = k * NTHR + tid;
        const uint32_t w = bm[j >> 5];
        const uint32_t bit = 1u << (j & 31);
        if (w & bit) {
            const int pos = wpre[j >> 5] + __popc(w & (bit - 1u));
            ssA[pos] = sA[j];
            ssB[pos] = sB[j];
            ssC[pos] = sC[j];
        }
    }
    __syncthreads();
    const int cnt = wpre[NG / 32];

    // ---- Phase B3: 2-segment front-to-back composite.
    const int ppix = tid & (NPIX - 1);
    const int seg  = tid >> 7;
    const int x = blockIdx.x * TW + (ppix & (TW - 1));
    const int y = blockIdx.y * TH + (ppix >> 4);
    const float fx = (float)x;
    const float fy = (float)y;

    const int half = (cnt + 1) >> 1;
    const int nbeg = seg ? half : 0;
    const int nend = seg ? cnt : half;

    float T = 1.0f, aR = 0.0f, aG = 0.0f, aB = 0.0f, aD = 0.0f;

    for (int n = nbeg; n < nend; ++n) {
        const float4 A = ssA[n];
        const float dx = fx - A.x;
        const float dy = fy - A.y;
        const float4 B = ssB[n];
        const float power = -0.5f * (A.z * dx * dx) - A.w * dx * dy
                            - 0.5f * (B.x * dy * dy);
        if (power > 0.0f) continue;
        const float alpha = fminf(0.99f, B.y * __expf(power));
        if (alpha < (1.0f / 255.0f)) continue;
        const float4 C = ssC[n];
        const float w = alpha * T;
        aR += w * B.z;
        aG += w * B.w;
        aB += w * C.x;
        aD += w * C.y;
        T *= (1.0f - alpha);
        if (T < 1e-7f) break;
    }

    if (seg == 1) {
        sT1[ppix] = T; sR1[ppix] = aR; sG1[ppix] = aG;
        sB1[ppix] = aB; sD1[ppix] = aD;
    }
    __syncthreads();

    if (seg == 0) {
        const float T1 = sT1[ppix];
        const float fR = aR + T * sR1[ppix];
        const float fG = aG + T * sG1[ppix];
        const float fB = aB + T * sB1[ppix];
        const float fD = aD + T * sD1[ppix];
        const float Tf = T * T1;

        const int pix = y * IMG_W + x;
        const float m = mask[pix];
        const int HW = IMG_H * IMG_W;
        out[0 * HW + pix] = (fR + Tf * bg[0]) * m;
        out[1 * HW + pix] = (fG + Tf * bg[1]) * m;
        out[2 * HW + pix] = (fB + Tf * bg[2]) * m;
        out[3 * HW + NG + pix] = fD * m;   // invd after color(3*HW) + radii(NG)
    }
}

// ---------------------------------------------------------------------------
extern "C" void kernel_launch(void* const* d_in, const int* in_sizes, int n_in,
                              void* d_out, int out_size)
{
    const float* means3D = (const float*)d_in[0];
    // d_in[1] = means2D (unused by reference math)
    const float* opac    = (const float*)d_in[2];
    const float* colors  = (const float*)d_in[3];
    const float* scales  = (const float*)d_in[4];
    const float* rots    = (const float*)d_in[5];
    const float* view    = (const float*)d_in[6];
    const float* proj    = (const float*)d_in[7];
    const float* bg      = (const float*)d_in[8];
    const float* mask    = (const float*)d_in[9];
    float* out = (float*)d_out;

    dim3 blk(NTHR);
    dim3 grd(IMG_W / TW, IMG_H / TH);   // 16 x 32 = 512 blocks == NG
    fused_kernel<<<grd, blk>>>(means3D, opac, colors, scales, rots,
                               view, proj, bg, mask, out);
}

// round 17
// speedup vs baseline: 1.1353x; 1.1324x over previous
#include <cuda_runtime.h>
#include <math.h>
#include <stdint.h>

#define NG 512
#define IMG_H 256
#define IMG_W 256
#define TW 16
#define TH 8
#define NPIX 128          // pixels per tile
#define NTHR 256          // 2 threads per pixel (2 composite segments)

#define FXC 256.0f
#define FYC 256.0f
#define LIMX (1.3f * 0.5f)
#define LIMY (1.3f * 0.5f)

// Per-gaussian preprocessed data (unsorted, indexed by gaussian id):
//  gA: px, py, ca, cb        gB: cc, op, cr, cg
//  gC: cb(blue), invdepth, depth, r2
//  gCull: px, py, r2 (cull radius^2; <0 => never visible), depth
__device__ float4 gA[NG];
__device__ float4 gB[NG];
__device__ float4 gC[NG];
__device__ float4 gCull[NG];

// ---------------------------------------------------------------------------
// Preprocess (R8-proven, cheapest measured front-end): one thread per
// gaussian; all MUFU-heavy math exactly once; NO global sort.
// ---------------------------------------------------------------------------
__global__ void __launch_bounds__(64)
preprocess_kernel(const float* __restrict__ means3D,
                  const float* __restrict__ opac,
                  const float* __restrict__ colors,
                  const float* __restrict__ scales,
                  const float* __restrict__ rots,
                  const float* __restrict__ view,
                  const float* __restrict__ proj,
                  float* __restrict__ radii_out)
{
    const int j = blockIdx.x * 64 + threadIdx.x;
    if (j >= NG) return;

    const float V00 = view[0], V01 = view[1], V02 = view[2],  V03 = view[3];
    const float V10 = view[4], V11 = view[5], V12 = view[6],  V13 = view[7];
    const float V20 = view[8], V21 = view[9], V22 = view[10], V23 = view[11];

    const float m0 = means3D[3 * j + 0];
    const float m1 = means3D[3 * j + 1];
    const float m2 = means3D[3 * j + 2];

    const float t0 = V00 * m0 + V01 * m1 + V02 * m2 + V03;
    const float t1 = V10 * m0 + V11 * m1 + V12 * m2 + V13;
    const float depth = V20 * m0 + V21 * m1 + V22 * m2 + V23;

    const float c0 = proj[0]  * m0 + proj[1]  * m1 + proj[2]  * m2 + proj[3];
    const float c1 = proj[4]  * m0 + proj[5]  * m1 + proj[6]  * m2 + proj[7];
    const float c3 = proj[12] * m0 + proj[13] * m1 + proj[14] * m2 + proj[15];
    const float pw = __fdividef(1.0f, c3 + 1e-7f);
    const float px = ((c0 * pw + 1.0f) * (float)IMG_W - 1.0f) * 0.5f;
    const float py = ((c1 * pw + 1.0f) * (float)IMG_H - 1.0f) * 0.5f;

    const float4 q = reinterpret_cast<const float4*>(rots)[j];
    float qw = q.x, qx = q.y, qy = q.z, qz = q.w;
    const float qn = rsqrtf(qw * qw + qx * qx + qy * qy + qz * qz);
    qw *= qn; qx *= qn; qy *= qn; qz *= qn;
    const float R00 = 1.0f - 2.0f * (qy * qy + qz * qz);
    const float R01 = 2.0f * (qx * qy - qw * qz);
    const float R02 = 2.0f * (qx * qz + qw * qy);
    const float R10 = 2.0f * (qx * qy + qw * qz);
    const float R11 = 1.0f - 2.0f * (qx * qx + qz * qz);
    const float R12 = 2.0f * (qy * qz - qw * qx);
    const float R20 = 2.0f * (qx * qz - qw * qy);
    const float R21 = 2.0f * (qy * qz + qw * qx);
    const float R22 = 1.0f - 2.0f * (qx * qx + qy * qy);

    const float s0 = scales[3 * j + 0];
    const float s1 = scales[3 * j + 1];
    const float s2 = scales[3 * j + 2];

    const float M00 = R00 * s0, M01 = R01 * s1, M02 = R02 * s2;
    const float M10 = R10 * s0, M11 = R11 * s1, M12 = R12 * s2;
    const float M20 = R20 * s0, M21 = R21 * s1, M22 = R22 * s2;
    const float C00 = M00 * M00 + M01 * M01 + M02 * M02;
    const float C01 = M00 * M10 + M01 * M11 + M02 * M12;
    const float C02 = M00 * M20 + M01 * M21 + M02 * M22;
    const float C11 = M10 * M10 + M11 * M11 + M12 * M12;
    const float C12 = M10 * M20 + M11 * M21 + M12 * M22;
    const float C22 = M20 * M20 + M21 * M21 + M22 * M22;

    const float invz = __fdividef(1.0f, depth);
    const float ttx = fminf(fmaxf(t0 * invz, -LIMX), LIMX) * depth;
    const float tty = fminf(fmaxf(t1 * invz, -LIMY), LIMY) * depth;
    const float J00 = FXC * invz;
    const float J02 = -FXC * ttx * invz * invz;
    const float J11 = FYC * invz;
    const float J12 = -FYC * tty * invz * invz;

    const float T00 = J00 * V00 + J02 * V20;
    const float T01 = J00 * V01 + J02 * V21;
    const float T02 = J00 * V02 + J02 * V22;
    const float T10 = J11 * V10 + J12 * V20;
    const float T11 = J11 * V11 + J12 * V21;
    const float T12 = J11 * V12 + J12 * V22;

    const float u0 = C00 * T00 + C01 * T01 + C02 * T02;
    const float u1 = C01 * T00 + C11 * T01 + C12 * T02;
    const float u2 = C02 * T00 + C12 * T01 + C22 * T02;
    const float w0 = C00 * T10 + C01 * T11 + C02 * T12;
    const float w1 = C01 * T10 + C11 * T11 + C12 * T12;
    const float w2 = C02 * T10 + C12 * T11 + C22 * T12;
    const float a = T00 * u0 + T01 * u1 + T02 * u2 + 0.3f;
    const float b = T10 * u0 + T11 * u1 + T12 * u2;
    const float c = T10 * w0 + T11 * w1 + T12 * w2 + 0.3f;

    const float det = a * c - b * b;
    const float inv_det = __fdividef(1.0f, (det != 0.0f) ? det : 1.0f);
    const float ca =  c * inv_det;
    const float cb = -b * inv_det;
    const float cc =  a * inv_det;

    const float mid = 0.5f * (a + c);
    const float lam = mid + sqrtf(fmaxf(mid * mid - det, 0.1f));

    radii_out[j] = (float)((int)ceilf(3.0f * sqrtf(lam)));

    const bool valid = (depth > 0.2f) && (det > 0.0f);
    const float op = opac[j];

    // Exact cull radius^2: alpha < 1/255 guaranteed beyond it.
    float r2 = -1.0f;
    if (valid && op * 255.0f > 1.0f) {
        r2 = 2.0f * lam * __logf(255.0f * op) + 1e-2f;
        if (r2 < 0.0f) r2 = -1.0f;
    }

    gA[j] = make_float4(px, py, ca, cb);
    gB[j] = make_float4(cc, op, colors[3 * j + 0], colors[3 * j + 1]);
    gC[j] = make_float4(colors[3 * j + 2],
                        __fdividef(1.0f, fmaxf(depth, 1e-6f)),
                        depth, r2);
    gCull[j] = make_float4(px, py, r2, depth);
}

// ---------------------------------------------------------------------------
// Raster: each block = one 16x8 tile, 256 threads. Ballot-cull (2 iters per
// thread, 1 LDG each), warp-shfl prefix, compact survivors in id order,
// per-tile rank-sort survivors by (depth, id) with one thread per survivor,
// then 2-segment front-to-back composite per pixel:
//   final = part0 + T0*part1,  T = T0*T1.
// ---------------------------------------------------------------------------
__global__ void __launch_bounds__(NTHR)
raster_kernel(const float* __restrict__ bg,
              const float* __restrict__ mask,
              float* __restrict__ out)
{
    __shared__ float4 ssA[NG];
    __shared__ float4 ssB[NG];
    __shared__ float4 ssC[NG];
    __shared__ int    ord[NG];
    __shared__ uint32_t bm[NG / 32];
    __shared__ int wpre[NG / 32 + 1];
    __shared__ float sT1[NPIX], sR1[NPIX], sG1[NPIX], sB1[NPIX], sD1[NPIX];

    const int tid  = threadIdx.x;
    const int warp = tid >> 5;          // 0..7
    const int lane = tid & 31;

    const float tx0 = (float)(blockIdx.x * TW);
    const float tx1 = tx0 + (float)(TW - 1);
    const float ty0 = (float)(blockIdx.y * TH);
    const float ty1 = ty0 + (float)(TH - 1);

    // Phase 1: cull. j = k*256 + tid -> word index k*8 + warp.
    #pragma unroll
    for (int k = 0; k < NG / NTHR; ++k) {
        const int j = k * NTHR + tid;
        const float4 cg = gCull[j];
        const float cx = fminf(fmaxf(cg.x, tx0), tx1);
        const float cy = fminf(fmaxf(cg.y, ty0), ty1);
        const float ddx = cg.x - cx;
        const float ddy = cg.y - cy;
        const uint32_t bal = __ballot_sync(0xFFFFFFFFu,
                                           ddx * ddx + ddy * ddy <= cg.z);
        if (lane == 0) bm[k * 8 + warp] = bal;
    }
    __syncthreads();

    // Warp-parallel exclusive prefix over 16 word-popcounts (warp 0).
    if (warp == 0) {
        int v = (lane < NG / 32) ? (int)__popc(bm[lane]) : 0;
        #pragma unroll
        for (int off = 1; off < NG / 32; off <<= 1) {
            const int n = __shfl_up_sync(0xFFFFFFFFu, v, off);
            if (lane >= off) v += n;
        }
        if (lane < NG / 32) wpre[lane + 1] = v;
        if (lane == 0) wpre[0] = 0;
    }
    __syncthreads();

    // Phase 2: compaction (preserves gaussian-id order); survivor data
    // loaded from global only here.
    #pragma unroll
    for (int k = 0; k < NG / NTHR; ++k) {
        const int j = k * NTHR + tid;
        const uint32_t w = bm[j >> 5];
        const uint32_t bit = 1u << (j & 31);
        if (w & bit) {
            const int pos = wpre[j >> 5] + __popc(w & (bit - 1u));
            ssA[pos] = gA[j];
            ssB[pos] = gB[j];
            ssC[pos] = gC[j];
        }
    }
    __syncthreads();
    const int cnt = wpre[NG / 32];

    // Phase 3: rank-sort survivors by (depth, id). Slots are in id order, so
    // the id tie-break is the slot index. One thread per survivor.
    for (int e = tid; e < cnt; e += NTHR) {
        const float de = ssC[e].z;
        int rank = 0;
        for (int m = 0; m < cnt; ++m) {
            const float dm = ssC[m].z;
            rank += (dm < de) || ((dm == de) && (m < e));
        }
        ord[rank] = e;
    }
    __syncthreads();

    // Phase 4: 2-segment front-to-back composite.
    const int ppix = tid & (NPIX - 1);         // 0..127 local pixel
    const int seg  = tid >> 7;                 // 0 or 1
    const int x = blockIdx.x * TW + (ppix & (TW - 1));
    const int y = blockIdx.y * TH + (ppix >> 4);
    const float fx = (float)x;
    const float fy = (float)y;

    const int half = (cnt + 1) >> 1;
    const int nbeg = seg ? half : 0;
    const int nend = seg ? cnt : half;

    float T = 1.0f, aR = 0.0f, aG = 0.0f, aB = 0.0f, aD = 0.0f;

    for (int n = nbeg; n < nend; ++n) {
        const int pos = ord[n];
        const float4 A = ssA[pos];
        const float dx = fx - A.x;
        const float dy = fy - A.y;
        const float4 B = ssB[pos];
        const float power = -0.5f * (A.z * dx * dx) - A.w * dx * dy
                            - 0.5f * (B.x * dy * dy);
        if (power > 0.0f) continue;
        const float alpha = fminf(0.99f, B.y * __expf(power));
        if (alpha < (1.0f / 255.0f)) continue;
        const float4 C = ssC[pos];
        const float w = alpha * T;
        aR += w * B.z;
        aG += w * B.w;
        aB += w * C.x;
        aD += w * C.y;
        T *= (1.0f - alpha);
        if (T < 1e-7f) break;
    }

    if (seg == 1) {
        sT1[ppix] = T; sR1[ppix] = aR; sG1[ppix] = aG;
        sB1[ppix] = aB; sD1[ppix] = aD;
    }
    __syncthreads();

    if (seg == 0) {
        const float T1 = sT1[ppix];
        const float fR = aR + T * sR1[ppix];
        const float fG = aG + T * sG1[ppix];
        const float fB = aB + T * sB1[ppix];
        const float fD = aD + T * sD1[ppix];
        const float Tf = T * T1;

        const int pix = y * IMG_W + x;
        const float m = mask[pix];
        const int HW = IMG_H * IMG_W;
        out[0 * HW + pix] = (fR + Tf * bg[0]) * m;
        out[1 * HW + pix] = (fG + Tf * bg[1]) * m;
        out[2 * HW + pix] = (fB + Tf * bg[2]) * m;
        out[3 * HW + NG + pix] = fD * m;   // invd after color(3*HW) + radii(NG)
    }
}

// ---------------------------------------------------------------------------
extern "C" void kernel_launch(void* const* d_in, const int* in_sizes, int n_in,
                              void* d_out, int out_size)
{
    const float* means3D = (const float*)d_in[0];
    // d_in[1] = means2D (unused by reference math)
    const float* opac    = (const float*)d_in[2];
    const float* colors  = (const float*)d_in[3];
    const float* scales  = (const float*)d_in[4];
    const float* rots    = (const float*)d_in[5];
    const float* view    = (const float*)d_in[6];
    const float* proj    = (const float*)d_in[7];
    const float* bg      = (const float*)d_in[8];
    const float* mask    = (const float*)d_in[9];
    float* out = (float*)d_out;

    float* radii_out = out + 3 * IMG_H * IMG_W;

    preprocess_kernel<<<8, 64>>>(means3D, opac, colors, scales, rots,
                                 view, proj, radii_out);

    dim3 blk(NTHR);
    dim3 grd(IMG_W / TW, IMG_H / TH);
    raster_kernel<<<grd, blk>>>(bg, mask, out);
}